// round 4
// baseline (speedup 1.0000x reference)
#include <cuda_runtime.h>
#include <cstdint>

#define NN 32
#define CC 64
#define TT 512
#define VV 25
#define HH 3
#define TB 4
#define TOTAL (NN*CC*TT*VV)     // 26214400
#define CNT_F (NN*TT*VV)        // 409600

// dynamic smem layout (float offsets)
#define XS_STRIDE 108
#define YS_STRIDE 36
#define XH_OFF 0                // [64][108]
#define XL_OFF 6912
#define YH_OFF 13824            // [64][36]
#define YL_OFF 16128
#define AH_OFF 18432            // [3][32][36]
#define AL_OFF 21888
#define ST_OFF 25344            // [128]
#define SM_FLOATS 25472
#define SM_BYTES (SM_FLOATS*4)  // 101888

__device__ float g_conv[TOTAL];
__device__ float g_Whi[HH*CC*CC];
__device__ float g_Wlo[HH*CC*CC];
__device__ float g_stats[128];
__device__ float g_scale[CC];
__device__ float g_shift[CC];

__device__ __forceinline__ float tf32r(float x) {
    uint32_t r; asm("cvt.rna.tf32.f32 %0, %1;" : "=r"(r) : "f"(x));
    return __uint_as_float(r);
}
__device__ __forceinline__ void mma8(float* c, const uint32_t* a, uint32_t b0, uint32_t b1) {
    asm volatile("mma.sync.aligned.m16n8k8.row.col.f32.tf32.tf32.f32 "
        "{%0,%1,%2,%3},{%4,%5,%6,%7},{%8,%9},{%0,%1,%2,%3};"
        : "+f"(c[0]), "+f"(c[1]), "+f"(c[2]), "+f"(c[3])
        : "r"(a[0]), "r"(a[1]), "r"(a[2]), "r"(a[3]), "r"(b0), "r"(b1));
}
__device__ __forceinline__ uint32_t f2u(float x) { return __float_as_uint(x); }

// ---------------------------------------------------------------------------
// prep: split W into tf32 hi/lo, zero stats
// ---------------------------------------------------------------------------
__global__ void prep_k(const float* __restrict__ W) {
    int i = blockIdx.x * blockDim.x + threadIdx.x;
    if (i < HH*CC*CC) {
        float w = W[i];
        float hi = tf32r(w);
        g_Whi[i] = hi;
        g_Wlo[i] = tf32r(w - hi);
    }
    if (i < 128) g_stats[i] = 0.f;
}

// ---------------------------------------------------------------------------
// conv via tensor cores (3xTF32): CTA = (n, 4 consecutive t)
// warp w owns output rows o in [16w, 16w+16)
// ---------------------------------------------------------------------------
__global__ __launch_bounds__(128, 2) void conv_mma(const float* __restrict__ x,
                                                   const float* __restrict__ A) {
    extern __shared__ float sm[];
    float* Xh = sm + XH_OFF;  float* Xl = sm + XL_OFF;
    float* Yh = sm + YH_OFF;  float* Yl = sm + YL_OFF;
    float* Ah = sm + AH_OFF;  float* Al = sm + AL_OFF;
    float* St = sm + ST_OFF;

    const int tid  = threadIdx.x;
    const int warp = tid >> 5, lane = tid & 31;
    const int grp  = lane >> 2, tig = lane & 3;
    const int o0   = warp * 16;
    const int n    = blockIdx.x >> 7;            // 128 t-blocks per n
    const int t0   = (blockIdx.x & 127) * TB;

    St[tid] = 0.f;

    // As fill: As[h][v][u] = tf32 split of A[h,v,u], zero-padded to 32x36
    for (int i = tid; i < HH*32*36; i += 128) {
        int h = i / (32*36); int rem = i - h*(32*36);
        int v = rem / 36, u = rem - v*36;
        float val = (v < VV && u < VV) ? A[(h*VV + v)*VV + u] : 0.f;
        float hi = tf32r(val);
        Ah[i] = hi; Al[i] = tf32r(val - hi);
    }
    // Ys pad zero (cols u = 25..35)
    for (int i = tid; i < 64*11; i += 128) {
        int r = i / 11, u = 25 + (i - r*11);
        Yh[r*YS_STRIDE + u] = 0.f; Yl[r*YS_STRIDE + u] = 0.f;
    }
    // Xs pad zero (cols s = 100..107)
    for (int i = tid; i < 64*8; i += 128) {
        int c = i >> 3, s = 100 + (i & 7);
        Xh[c*XS_STRIDE + s] = 0.f; Xl[c*XS_STRIDE + s] = 0.f;
    }
    // Xs fill: 100 contiguous floats per channel (4 t's), tf32 split
    {
        const float4* x4 = reinterpret_cast<const float4*>(x);
        for (int i = tid; i < CC*25; i += 128) {
            int c = i / 25, q = i - c*25;
            unsigned base = ((unsigned)(n*CC + c)*TT + t0)*VV;   // divisible by 4
            float4 v = x4[(base >> 2) + q];
            float vv[4] = {v.x, v.y, v.z, v.w};
            #pragma unroll
            for (int e = 0; e < 4; ++e) {
                float hi = tf32r(vv[e]);
                int s = q*4 + e;
                Xh[c*XS_STRIDE + s] = hi;
                Xl[c*XS_STRIDE + s] = tf32r(vv[e] - hi);
            }
        }
    }
    __syncthreads();

    float OUT[TB][4][4];
    #pragma unroll
    for (int t = 0; t < TB; ++t)
        #pragma unroll
        for (int j = 0; j < 4; ++j)
            #pragma unroll
            for (int e = 0; e < 4; ++e) OUT[t][j][e] = 0.f;

    for (int h = 0; h < HH; ++h) {
        // ---- MMA1: Y[o, t*32+u] = W_h[o,c] @ X[c, t*25+u], 3xTF32 ----
        float Yacc[TB][4][4];
        #pragma unroll
        for (int t = 0; t < TB; ++t)
            #pragma unroll
            for (int j = 0; j < 4; ++j)
                #pragma unroll
                for (int e = 0; e < 4; ++e) Yacc[t][j][e] = 0.f;

        #pragma unroll
        for (int k = 0; k < 8; ++k) {
            // W fragments: a0(grp,tig) a1(grp+8,tig) a2(grp,tig+4) a3(grp+8,tig+4)
            int wb = (h*CC + o0 + grp)*CC + 8*k + tig;
            uint32_t whi[4], wlo[4];
            whi[0] = f2u(g_Whi[wb]);          wlo[0] = f2u(g_Wlo[wb]);
            whi[1] = f2u(g_Whi[wb + 8*CC]);   wlo[1] = f2u(g_Wlo[wb + 8*CC]);
            whi[2] = f2u(g_Whi[wb + 4]);      wlo[2] = f2u(g_Wlo[wb + 4]);
            whi[3] = f2u(g_Whi[wb + 8*CC+4]); wlo[3] = f2u(g_Wlo[wb + 8*CC+4]);
            #pragma unroll
            for (int t = 0; t < TB; ++t) {
                #pragma unroll
                for (int j = 0; j < 4; ++j) {
                    int col = t*25 + 8*j + grp;
                    int r0 = (8*k + tig)*XS_STRIDE + col;
                    int r1 = r0 + 4*XS_STRIDE;
                    uint32_t bh0 = f2u(Xh[r0]), bh1 = f2u(Xh[r1]);
                    uint32_t bl0 = f2u(Xl[r0]), bl1 = f2u(Xl[r1]);
                    mma8(Yacc[t][j], whi, bh0, bh1);
                    mma8(Yacc[t][j], whi, bl0, bl1);
                    mma8(Yacc[t][j], wlo, bh0, bh1);
                }
            }
        }

        // ---- per t: Y split -> smem, then MMA2: OUT += Y @ A_h^T (3xTF32) ----
        #pragma unroll
        for (int t = 0; t < TB; ++t) {
            __syncwarp();                  // prior reads of Ys done before overwrite
            #pragma unroll
            for (int j = 0; j < 4; ++j) {
                #pragma unroll
                for (int e = 0; e < 4; ++e) {
                    int row = o0 + grp + ((e >= 2) ? 8 : 0);
                    int u   = 8*j + 2*tig + (e & 1);
                    if (u < VV) {
                        float y  = Yacc[t][j][e];
                        float yh = tf32r(y);
                        Yh[row*YS_STRIDE + u] = yh;
                        Yl[row*YS_STRIDE + u] = tf32r(y - yh);
                    }
                }
            }
            __syncwarp();
            #pragma unroll
            for (int k2 = 0; k2 < 4; ++k2) {
                int yb = (o0 + grp)*YS_STRIDE + 8*k2 + tig;
                uint32_t ah[4], al[4];
                ah[0] = f2u(Yh[yb]);                   al[0] = f2u(Yl[yb]);
                ah[1] = f2u(Yh[yb + 8*YS_STRIDE]);     al[1] = f2u(Yl[yb + 8*YS_STRIDE]);
                ah[2] = f2u(Yh[yb + 4]);               al[2] = f2u(Yl[yb + 4]);
                ah[3] = f2u(Yh[yb + 8*YS_STRIDE + 4]); al[3] = f2u(Yl[yb + 8*YS_STRIDE + 4]);
                #pragma unroll
                for (int jv = 0; jv < 4; ++jv) {
                    // B[k=u, n=v] = A_h[v, u]; b0=(u0+tig, v0+grp), b1=(u0+tig+4, ...)
                    int ab = h*1152 + (8*jv + grp)*36 + 8*k2 + tig;
                    uint32_t bh0 = f2u(Ah[ab]), bh1 = f2u(Ah[ab + 4]);
                    uint32_t bl0 = f2u(Al[ab]), bl1 = f2u(Al[ab + 4]);
                    mma8(OUT[t][jv], ah, bh0, bh1);
                    mma8(OUT[t][jv], ah, bl0, bl1);
                    mma8(OUT[t][jv], al, bh0, bh1);
                }
            }
        }
    }

    // ---- epilogue: stage OUT into Xh (reuse), stats, coalesced store ----
    __syncthreads();          // all MMA1 reads of Xs finished
    #pragma unroll
    for (int t = 0; t < TB; ++t)
        #pragma unroll
        for (int jv = 0; jv < 4; ++jv)
            #pragma unroll
            for (int e = 0; e < 4; ++e) {
                int row = o0 + grp + ((e >= 2) ? 8 : 0);
                int v   = 8*jv + 2*tig + (e & 1);
                if (v < VV) Xh[row*XS_STRIDE + t*VV + v] = OUT[t][jv][e];
            }
    __syncthreads();

    float4* cv4 = reinterpret_cast<float4*>(g_conv);
    for (int i = tid; i < CC*25; i += 128) {
        int o = i / 25, q = i - o*25;
        float4 f = *reinterpret_cast<const float4*>(Xh + o*XS_STRIDE + q*4);
        float s1 = f.x + f.y + f.z + f.w;
        float s2 = f.x*f.x + f.y*f.y + f.z*f.z + f.w*f.w;
        atomicAdd(&St[o], s1);
        atomicAdd(&St[64 + o], s2);
        unsigned base = ((unsigned)(n*CC + o)*TT + t0)*VV;
        cv4[(base >> 2) + q] = f;
    }
    __syncthreads();
    atomicAdd(&g_stats[tid], St[tid]);
}

// ---------------------------------------------------------------------------
__global__ void stats_k(const float* __restrict__ gamma, const float* __restrict__ beta) {
    int o = threadIdx.x;
    if (o < CC) {
        const float inv = 1.f / (float)CNT_F;
        float mean = g_stats[o] * inv;
        float var  = g_stats[64 + o] * inv - mean*mean;
        float sc = gamma[o] * rsqrtf(var + 1e-5f);
        g_scale[o] = sc;
        g_shift[o] = beta[o] - mean*sc;
    }
}

__global__ void bn_apply(const float4* __restrict__ xv, float4* __restrict__ ov) {
    const float4* cv = reinterpret_cast<const float4*>(g_conv);
    const int n4 = TOTAL / 4;
    int stride = gridDim.x * blockDim.x;
    for (int i = blockIdx.x * blockDim.x + threadIdx.x; i < n4; i += stride) {
        int c = (i / 3200) & 63;
        float s  = __ldg(&g_scale[c]);
        float sh = __ldg(&g_shift[c]);
        float4 a = cv[i];
        float4 b = xv[i];
        float4 r;
        r.x = fmaxf(fmaf(s, a.x, sh) + b.x, 0.f);
        r.y = fmaxf(fmaf(s, a.y, sh) + b.y, 0.f);
        r.z = fmaxf(fmaf(s, a.z, sh) + b.z, 0.f);
        r.w = fmaxf(fmaf(s, a.w, sh) + b.w, 0.f);
        ov[i] = r;
    }
}

// ---------------------------------------------------------------------------
extern "C" void kernel_launch(void* const* d_in, const int* in_sizes, int n_in,
                              void* d_out, int out_size) {
    const float* x     = (const float*)d_in[0];
    const float* A     = (const float*)d_in[1];
    const float* W     = (const float*)d_in[2];
    // d_in[3] = b : cancels exactly under training-mode BatchNorm -> unused
    const float* gamma = (const float*)d_in[4];
    const float* beta  = (const float*)d_in[5];
    float* out = (float*)d_out;

    cudaFuncSetAttribute(conv_mma, cudaFuncAttributeMaxDynamicSharedMemorySize, SM_BYTES);

    prep_k<<<48, 256>>>(W);
    conv_mma<<<NN*(TT/TB), 128, SM_BYTES>>>(x, A);
    stats_k<<<1, 64>>>(gamma, beta);
    bn_apply<<<4096, 256>>>(reinterpret_cast<const float4*>(x),
                            reinterpret_cast<float4*>(out));
}

// round 5
// speedup vs baseline: 1.3644x; 1.3644x over previous
#include <cuda_runtime.h>
#include <cuda_fp16.h>
#include <cstdint>

#define NN 32
#define CC 64
#define TT 512
#define VV 25
#define HH 3
#define TB 4
#define TOTAL (NN*CC*TT*VV)     // 26214400
#define CNT_F (NN*TT*VV)        // 409600

// smem byte offsets
#define XH_B 0                  // half [128][72]
#define XL_B 18432
#define WH_B 36864              // half [3*64][72]
#define WL_B 64512
#define AH_B 92160              // half [3*32][40]
#define AL_B 99840
#define ST_B 107520             // float [128]
#define SM_BYTES 108032

__device__ float  g_conv[TOTAL];
__device__ __half g_Whi[HH*CC*CC];
__device__ __half g_Wlo[HH*CC*CC];
__device__ float  g_stats[128];
__device__ float  g_scale[CC];
__device__ float  g_shift[CC];

__device__ __forceinline__ uint32_t smem_u32(const void* p) {
    uint32_t a;
    asm("{ .reg .u64 t; cvta.to.shared.u64 t, %1; cvt.u32.u64 %0, t; }" : "=r"(a) : "l"(p));
    return a;
}
__device__ __forceinline__ void ldmx4(uint32_t& r0, uint32_t& r1, uint32_t& r2, uint32_t& r3, uint32_t a) {
    asm volatile("ldmatrix.sync.aligned.m8n8.x4.shared.b16 {%0,%1,%2,%3},[%4];"
                 : "=r"(r0), "=r"(r1), "=r"(r2), "=r"(r3) : "r"(a));
}
__device__ __forceinline__ void ldmx2(uint32_t& r0, uint32_t& r1, uint32_t a) {
    asm volatile("ldmatrix.sync.aligned.m8n8.x2.shared.b16 {%0,%1},[%2];"
                 : "=r"(r0), "=r"(r1) : "r"(a));
}
__device__ __forceinline__ void mma16(float* c, const uint32_t* a, uint32_t b0, uint32_t b1) {
    asm volatile("mma.sync.aligned.m16n8k16.row.col.f32.f16.f16.f32 "
        "{%0,%1,%2,%3},{%4,%5,%6,%7},{%8,%9},{%0,%1,%2,%3};"
        : "+f"(c[0]), "+f"(c[1]), "+f"(c[2]), "+f"(c[3])
        : "r"(a[0]), "r"(a[1]), "r"(a[2]), "r"(a[3]), "r"(b0), "r"(b1));
}
__device__ __forceinline__ uint32_t h2u(__half2 h) { return *reinterpret_cast<uint32_t*>(&h); }

// ---------------------------------------------------------------------------
__global__ void prep_k(const float* __restrict__ W) {
    int i = blockIdx.x * blockDim.x + threadIdx.x;
    if (i < HH*CC*CC) {
        float w = W[i];
        __half hi = __float2half_rn(w);
        g_Whi[i] = hi;
        g_Wlo[i] = __float2half_rn(w - __half2float(hi));
    }
    if (i < 128) g_stats[i] = 0.f;
}

// ---------------------------------------------------------------------------
// conv via fp16 2-split mma.m16n8k16 + ldmatrix. CTA = (n, 4 t's).
// warp w owns output rows o in [16w, 16w+16).
// stage1: Y[o, 32t+u] = W_h[o,c] @ Xt[c, 32t+u]   (u padded 25->32)
// stage2: OUT[o, v]  += Y[o,u] @ A_h[v,u]^T       (A-frags built in-register)
// ---------------------------------------------------------------------------
__global__ __launch_bounds__(128, 2) void conv_mma(const float* __restrict__ x,
                                                   const float* __restrict__ A) {
    extern __shared__ char sm[];
    __half* Xh = (__half*)(sm + XH_B);
    __half* Xl = (__half*)(sm + XL_B);
    __half* Wh = (__half*)(sm + WH_B);
    __half* Wl = (__half*)(sm + WL_B);
    __half* Ah = (__half*)(sm + AH_B);
    __half* Al = (__half*)(sm + AL_B);
    float*  St = (float*)(sm + ST_B);

    const uint32_t smb = smem_u32(sm);
    const int tid  = threadIdx.x;
    const int warp = tid >> 5, lane = tid & 31;
    const int grp  = lane >> 2, tig = lane & 3;
    const int o0   = warp * 16;
    const int n    = blockIdx.x >> 7;
    const int t0   = (blockIdx.x & 127) * TB;

    St[tid] = 0.f;

    // --- W smem: copy halves [192][64] -> rows stride 72 ---
    {
        const uint32_t* sh = reinterpret_cast<const uint32_t*>(g_Whi);
        const uint32_t* sl = reinterpret_cast<const uint32_t*>(g_Wlo);
        uint32_t* dh = reinterpret_cast<uint32_t*>(Wh);
        uint32_t* dl = reinterpret_cast<uint32_t*>(Wl);
        for (int i = tid; i < 192*32; i += 128) {
            int r = i >> 5, c2 = i & 31;
            dh[r*36 + c2] = sh[i];      // 72 halves = 36 u32 per row
            dl[r*36 + c2] = sl[i];
        }
    }
    // --- A smem: [3*32][40] halves, zero-padded beyond 25x25 ---
    for (int i = tid; i < HH*32*32; i += 128) {
        int h = i >> 10, rem = i & 1023;
        int v = rem >> 5, u = rem & 31;
        float val = (v < VV && u < VV) ? A[(h*VV + v)*VV + u] : 0.f;
        __half hi = __float2half_rn(val);
        Ah[(h*32 + v)*40 + u] = hi;
        Al[(h*32 + v)*40 + u] = __float2half_rn(val - __half2float(hi));
    }
    // --- X pad rows (u=25..31): zero cols 0..63 ---
    for (int i = tid; i < 28*64; i += 128) {
        int r = i >> 6, c = i & 63;
        int row = (r / 7)*32 + 25 + (r % 7);
        Xh[row*72 + c] = __float2half(0.f);
        Xl[row*72 + c] = __float2half(0.f);
    }
    // --- X fill transposed: Xs[32t+u][c] from x[n,c,t0+t,u] ---
    {
        const float4* x4 = reinterpret_cast<const float4*>(x);
        for (int i = tid; i < CC*25; i += 128) {
            int c = i / 25, q = i - c*25;
            unsigned base = ((unsigned)(n*CC + c)*TT + t0)*VV;
            float4 v = x4[(base >> 2) + q];
            float vv[4] = {v.x, v.y, v.z, v.w};
            #pragma unroll
            for (int e = 0; e < 4; ++e) {
                int s = q*4 + e;
                int row = (s / VV)*32 + (s % VV);
                __half hi = __float2half_rn(vv[e]);
                Xh[row*72 + c] = hi;
                Xl[row*72 + c] = __float2half_rn(vv[e] - __half2float(hi));
            }
        }
    }
    __syncthreads();

    float OUT[TB][4][4];
    #pragma unroll
    for (int t = 0; t < TB; ++t)
        #pragma unroll
        for (int j = 0; j < 4; ++j)
            #pragma unroll
            for (int e = 0; e < 4; ++e) OUT[t][j][e] = 0.f;

    // ldmatrix address components
    const int q4 = lane >> 3, r8 = lane & 7;          // x4 quadrant / row
    const int wrow = r8 + ((q4 & 1) ? 8 : 0);
    const int wcol8 = (q4 & 2) ? 8 : 0;
    const int brow = lane & 7;                         // x2 row
    const int bcol8 = (lane & 8) ? 8 : 0;

    for (int h = 0; h < HH; ++h) {
        // ---- stage 1 ----
        float Y[16][4];
        #pragma unroll
        for (int nn = 0; nn < 16; ++nn)
            #pragma unroll
            for (int e = 0; e < 4; ++e) Y[nn][e] = 0.f;

        #pragma unroll
        for (int kk = 0; kk < 4; ++kk) {
            uint32_t wh[4], wl[4];
            {
                uint32_t off = (uint32_t)(((h*64 + o0 + wrow)*72) + kk*16 + wcol8) * 2;
                ldmx4(wh[0], wh[1], wh[2], wh[3], smb + WH_B + off);
                ldmx4(wl[0], wl[1], wl[2], wl[3], smb + WL_B + off);
            }
            #pragma unroll
            for (int nn = 0; nn < 16; ++nn) {
                uint32_t boff = (uint32_t)((8*nn + brow)*72 + kk*16 + bcol8) * 2;
                uint32_t bh0, bh1, bl0, bl1;
                ldmx2(bh0, bh1, smb + XH_B + boff);
                ldmx2(bl0, bl1, smb + XL_B + boff);
                mma16(Y[nn], wh, bh0, bh1);
                mma16(Y[nn], wh, bl0, bl1);
                mma16(Y[nn], wl, bh0, bh1);
            }
        }

        // ---- stage 2 B-fragments for this head (v-tiles x k-tiles) ----
        uint32_t B2h[4][2][2], B2l[4][2][2];
        #pragma unroll
        for (int nv = 0; nv < 4; ++nv)
            #pragma unroll
            for (int kp = 0; kp < 2; ++kp) {
                uint32_t off = (uint32_t)(((h*32 + 8*nv + brow)*40) + kp*16 + bcol8) * 2;
                ldmx2(B2h[nv][kp][0], B2h[nv][kp][1], smb + AH_B + off);
                ldmx2(B2l[nv][kp][0], B2l[nv][kp][1], smb + AL_B + off);
            }

        // ---- stage 2: in-register Y -> A-frags, accumulate OUT ----
        #pragma unroll
        for (int t = 0; t < TB; ++t) {
            #pragma unroll
            for (int kp = 0; kp < 2; ++kp) {
                int n0 = 4*t + 2*kp;
                uint32_t ah[4], al[4];
                #pragma unroll
                for (int i = 0; i < 4; ++i) {
                    // i=0: Y[n0] c0,c1 | i=1: Y[n0] c2,c3 | i=2: Y[n0+1] c0,c1 | i=3: Y[n0+1] c2,c3
                    const float* yp = Y[n0 + (i >> 1)];
                    float p = yp[(i & 1) ? 2 : 0];
                    float qv = yp[(i & 1) ? 3 : 1];
                    __half2 hh = __floats2half2_rn(p, qv);
                    float2 bk = __half22float2(hh);
                    __half2 ll = __floats2half2_rn(p - bk.x, qv - bk.y);
                    ah[i] = h2u(hh);
                    al[i] = h2u(ll);
                }
                #pragma unroll
                for (int nv = 0; nv < 4; ++nv) {
                    mma16(OUT[t][nv], ah, B2h[nv][kp][0], B2h[nv][kp][1]);
                    mma16(OUT[t][nv], ah, B2l[nv][kp][0], B2l[nv][kp][1]);
                    mma16(OUT[t][nv], al, B2h[nv][kp][0], B2h[nv][kp][1]);
                }
            }
        }
    }

    // ---- epilogue: stage OUT -> smem [64][104], stats, coalesced store ----
    __syncthreads();
    float* Sout = (float*)sm;
    #pragma unroll
    for (int t = 0; t < TB; ++t)
        #pragma unroll
        for (int nv = 0; nv < 4; ++nv)
            #pragma unroll
            for (int e = 0; e < 4; ++e) {
                int row = o0 + grp + ((e >= 2) ? 8 : 0);
                int v   = 8*nv + 2*tig + (e & 1);
                if (v < VV) Sout[row*104 + t*VV + v] = OUT[t][nv][e];
            }
    __syncthreads();

    float4* cv4 = reinterpret_cast<float4*>(g_conv);
    for (int i = tid; i < CC*25; i += 128) {
        int o = i / 25, qq = i - o*25;
        float4 f = *reinterpret_cast<const float4*>(Sout + o*104 + qq*4);
        float s1 = f.x + f.y + f.z + f.w;
        float s2 = f.x*f.x + f.y*f.y + f.z*f.z + f.w*f.w;
        atomicAdd(&St[o], s1);
        atomicAdd(&St[64 + o], s2);
        unsigned base = ((unsigned)(n*CC + o)*TT + t0)*VV;
        cv4[(base >> 2) + qq] = f;
    }
    __syncthreads();
    atomicAdd(&g_stats[tid], St[tid]);
}

// ---------------------------------------------------------------------------
__global__ void stats_k(const float* __restrict__ gamma, const float* __restrict__ beta) {
    int o = threadIdx.x;
    if (o < CC) {
        const float inv = 1.f / (float)CNT_F;
        float mean = g_stats[o] * inv;
        float var  = g_stats[64 + o] * inv - mean*mean;
        float sc = gamma[o] * rsqrtf(var + 1e-5f);
        g_scale[o] = sc;
        g_shift[o] = beta[o] - mean*sc;
    }
}

__global__ void bn_apply(const float4* __restrict__ xv, float4* __restrict__ ov) {
    const float4* cv = reinterpret_cast<const float4*>(g_conv);
    const int n4 = TOTAL / 4;
    int stride = gridDim.x * blockDim.x;
    for (int i = blockIdx.x * blockDim.x + threadIdx.x; i < n4; i += stride) {
        int c = (i / 3200) & 63;
        float s  = __ldg(&g_scale[c]);
        float sh = __ldg(&g_shift[c]);
        float4 a = cv[i];
        float4 b = xv[i];
        float4 r;
        r.x = fmaxf(fmaf(s, a.x, sh) + b.x, 0.f);
        r.y = fmaxf(fmaf(s, a.y, sh) + b.y, 0.f);
        r.z = fmaxf(fmaf(s, a.z, sh) + b.z, 0.f);
        r.w = fmaxf(fmaf(s, a.w, sh) + b.w, 0.f);
        ov[i] = r;
    }
}

// ---------------------------------------------------------------------------
extern "C" void kernel_launch(void* const* d_in, const int* in_sizes, int n_in,
                              void* d_out, int out_size) {
    const float* x     = (const float*)d_in[0];
    const float* A     = (const float*)d_in[1];
    const float* W     = (const float*)d_in[2];
    // d_in[3] = b : cancels exactly under training-mode BatchNorm -> unused
    const float* gamma = (const float*)d_in[4];
    const float* beta  = (const float*)d_in[5];
    float* out = (float*)d_out;

    cudaFuncSetAttribute(conv_mma, cudaFuncAttributeMaxDynamicSharedMemorySize, SM_BYTES);

    prep_k<<<48, 256>>>(W);
    conv_mma<<<NN*(TT/TB), 128, SM_BYTES>>>(x, A);
    stats_k<<<1, 64>>>(gamma, beta);
    bn_apply<<<4096, 256>>>(reinterpret_cast<const float4*>(x),
                            reinterpret_cast<float4*>(out));
}

// round 6
// speedup vs baseline: 1.9611x; 1.4373x over previous
#include <cuda_runtime.h>
#include <cuda_fp16.h>
#include <cstdint>

#define NN 32
#define CC 64
#define TT 512
#define VV 25
#define HH 3
#define TB 4
#define TOTAL (NN*CC*TT*VV)     // 26214400
#define CNT_F (NN*TT*VV)        // 409600

// smem byte offsets
#define XH_B 0                  // half [128][72]
#define WH_B 18432              // half [3*64][72]
#define AH_B 46080              // half [3*32][40]
#define ST_B 53760              // float [128]
#define SM_BYTES 54272

__device__ float  g_conv[TOTAL];
__device__ __half g_Wh[HH*CC*CC];
__device__ float  g_stats[128];
__device__ float  g_scale[CC];
__device__ float  g_shift[CC];

__device__ __forceinline__ uint32_t smem_u32(const void* p) {
    uint32_t a;
    asm("{ .reg .u64 t; cvta.to.shared.u64 t, %1; cvt.u32.u64 %0, t; }" : "=r"(a) : "l"(p));
    return a;
}
__device__ __forceinline__ void ldmx4(uint32_t& r0, uint32_t& r1, uint32_t& r2, uint32_t& r3, uint32_t a) {
    asm volatile("ldmatrix.sync.aligned.m8n8.x4.shared.b16 {%0,%1,%2,%3},[%4];"
                 : "=r"(r0), "=r"(r1), "=r"(r2), "=r"(r3) : "r"(a));
}
__device__ __forceinline__ void ldmx2(uint32_t& r0, uint32_t& r1, uint32_t a) {
    asm volatile("ldmatrix.sync.aligned.m8n8.x2.shared.b16 {%0,%1},[%2];"
                 : "=r"(r0), "=r"(r1) : "r"(a));
}
__device__ __forceinline__ void mma16(float* c, const uint32_t* a, uint32_t b0, uint32_t b1) {
    asm volatile("mma.sync.aligned.m16n8k16.row.col.f32.f16.f16.f32 "
        "{%0,%1,%2,%3},{%4,%5,%6,%7},{%8,%9},{%0,%1,%2,%3};"
        : "+f"(c[0]), "+f"(c[1]), "+f"(c[2]), "+f"(c[3])
        : "r"(a[0]), "r"(a[1]), "r"(a[2]), "r"(a[3]), "r"(b0), "r"(b1));
}
__device__ __forceinline__ uint32_t h2u(__half2 h) { return *reinterpret_cast<uint32_t*>(&h); }

// ---------------------------------------------------------------------------
__global__ void prep_k(const float* __restrict__ W) {
    int i = blockIdx.x * blockDim.x + threadIdx.x;
    if (i < HH*CC*CC) g_Wh[i] = __float2half_rn(W[i]);
    if (i < 128) g_stats[i] = 0.f;
}

// ---------------------------------------------------------------------------
// conv via single-fp16 mma.m16n8k16 + ldmatrix, fp32 accum. CTA = (n, 4 t's).
// warp w owns output rows o in [16w, 16w+16).
// stage1: Y[o, 32t+u] = W_h[o,c] @ Xt[c, 32t+u]   (u padded 25->32)
// stage2: OUT[o, v]  += Y[o,u] @ A_h[v,u]^T       (A-frags built in-register)
// ---------------------------------------------------------------------------
__global__ __launch_bounds__(128, 3) void conv_mma(const float* __restrict__ x,
                                                   const float* __restrict__ A) {
    extern __shared__ char sm[];
    __half* Xh = (__half*)(sm + XH_B);
    __half* Wh = (__half*)(sm + WH_B);
    __half* Ah = (__half*)(sm + AH_B);
    float*  St = (float*)(sm + ST_B);

    const uint32_t smb = smem_u32(sm);
    const int tid  = threadIdx.x;
    const int warp = tid >> 5, lane = tid & 31;
    const int grp  = lane >> 2, tig = lane & 3;
    const int o0   = warp * 16;
    const int n    = blockIdx.x >> 7;
    const int t0   = (blockIdx.x & 127) * TB;

    St[tid] = 0.f;

    // --- W smem: copy halves [192][64] -> rows stride 72 ---
    {
        const uint32_t* sh = reinterpret_cast<const uint32_t*>(g_Wh);
        uint32_t* dh = reinterpret_cast<uint32_t*>(Wh);
        for (int i = tid; i < 192*32; i += 128) {
            int r = i >> 5, c2 = i & 31;
            dh[r*36 + c2] = sh[i];      // 72 halves = 36 u32 per row
        }
    }
    // --- A smem: [3*32][40] halves, zero-padded beyond 25x25 ---
    for (int i = tid; i < HH*32*32; i += 128) {
        int h = i >> 10, rem = i & 1023;
        int v = rem >> 5, u = rem & 31;
        float val = (v < VV && u < VV) ? A[(h*VV + v)*VV + u] : 0.f;
        Ah[(h*32 + v)*40 + u] = __float2half_rn(val);
    }
    // --- X pad rows (u=25..31): zero cols 0..63 ---
    for (int i = tid; i < 28*64; i += 128) {
        int r = i >> 6, c = i & 63;
        int row = (r / 7)*32 + 25 + (r % 7);
        Xh[row*72 + c] = __float2half(0.f);
    }
    // --- X fill transposed: Xs[32t+u][c] from x[n,c,t0+t,u] ---
    {
        const float4* x4 = reinterpret_cast<const float4*>(x);
        for (int i = tid; i < CC*25; i += 128) {
            int c = i / 25, q = i - c*25;
            unsigned base = ((unsigned)(n*CC + c)*TT + t0)*VV;
            float4 v = x4[(base >> 2) + q];
            float vv[4] = {v.x, v.y, v.z, v.w};
            #pragma unroll
            for (int e = 0; e < 4; ++e) {
                int s = q*4 + e;
                int row = (s / VV)*32 + (s % VV);
                Xh[row*72 + c] = __float2half_rn(vv[e]);
            }
        }
    }
    __syncthreads();

    float OUT[TB][4][4];
    #pragma unroll
    for (int t = 0; t < TB; ++t)
        #pragma unroll
        for (int j = 0; j < 4; ++j)
            #pragma unroll
            for (int e = 0; e < 4; ++e) OUT[t][j][e] = 0.f;

    // ldmatrix address components
    const int q4 = lane >> 3, r8 = lane & 7;
    const int wrow = r8 + ((q4 & 1) ? 8 : 0);
    const int wcol8 = (q4 & 2) ? 8 : 0;
    const int brow = lane & 7;
    const int bcol8 = (lane & 8) ? 8 : 0;

    for (int h = 0; h < HH; ++h) {
        // ---- hoist W fragments for this head: whf[kk][0..3] ----
        uint32_t whf[4][4];
        #pragma unroll
        for (int kk = 0; kk < 4; ++kk) {
            uint32_t off = (uint32_t)(((h*64 + o0 + wrow)*72) + kk*16 + wcol8) * 2;
            ldmx4(whf[kk][0], whf[kk][1], whf[kk][2], whf[kk][3], smb + WH_B + off);
        }
        // ---- hoist stage-2 B fragments (A matrix) ----
        uint32_t B2[4][2][2];
        #pragma unroll
        for (int nv = 0; nv < 4; ++nv)
            #pragma unroll
            for (int kp = 0; kp < 2; ++kp) {
                uint32_t off = (uint32_t)(((h*32 + 8*nv + brow)*40) + kp*16 + bcol8) * 2;
                ldmx2(B2[nv][kp][0], B2[nv][kp][1], smb + AH_B + off);
            }

        #pragma unroll
        for (int t = 0; t < TB; ++t) {
            // ---- stage 1 for this t: Y tiles j=0..3 (cols 32t+8j..) ----
            float Y[4][4];
            #pragma unroll
            for (int j = 0; j < 4; ++j)
                #pragma unroll
                for (int e = 0; e < 4; ++e) Y[j][e] = 0.f;

            #pragma unroll
            for (int kk = 0; kk < 4; ++kk) {
                #pragma unroll
                for (int j = 0; j < 4; ++j) {
                    uint32_t boff = (uint32_t)((32*t + 8*j + brow)*72 + kk*16 + bcol8) * 2;
                    uint32_t bh0, bh1;
                    ldmx2(bh0, bh1, smb + XH_B + boff);
                    mma16(Y[j], whf[kk], bh0, bh1);
                }
            }
            // ---- stage 2: in-register Y -> A-frags, accumulate OUT ----
            #pragma unroll
            for (int kp = 0; kp < 2; ++kp) {
                uint32_t ah[4];
                #pragma unroll
                for (int i = 0; i < 4; ++i) {
                    const float* yp = Y[2*kp + (i >> 1)];
                    float p  = yp[(i & 1) ? 2 : 0];
                    float qv = yp[(i & 1) ? 3 : 1];
                    ah[i] = h2u(__floats2half2_rn(p, qv));
                }
                #pragma unroll
                for (int nv = 0; nv < 4; ++nv)
                    mma16(OUT[t][nv], ah, B2[nv][kp][0], B2[nv][kp][1]);
            }
        }
    }

    // ---- epilogue: stage OUT -> smem [64][104], stats, coalesced store ----
    __syncthreads();
    float* Sout = (float*)sm;
    #pragma unroll
    for (int t = 0; t < TB; ++t)
        #pragma unroll
        for (int nv = 0; nv < 4; ++nv)
            #pragma unroll
            for (int e = 0; e < 4; ++e) {
                int row = o0 + grp + ((e >= 2) ? 8 : 0);
                int v   = 8*nv + 2*tig + (e & 1);
                if (v < VV) Sout[row*104 + t*VV + v] = OUT[t][nv][e];
            }
    __syncthreads();

    float4* cv4 = reinterpret_cast<float4*>(g_conv);
    for (int i = tid; i < CC*25; i += 128) {
        int o = i / 25, qq = i - o*25;
        float4 f = *reinterpret_cast<const float4*>(Sout + o*104 + qq*4);
        float s1 = f.x + f.y + f.z + f.w;
        float s2 = f.x*f.x + f.y*f.y + f.z*f.z + f.w*f.w;
        atomicAdd(&St[o], s1);
        atomicAdd(&St[64 + o], s2);
        unsigned base = ((unsigned)(n*CC + o)*TT + t0)*VV;
        cv4[(base >> 2) + qq] = f;
    }
    __syncthreads();
    atomicAdd(&g_stats[tid], St[tid]);
}

// ---------------------------------------------------------------------------
__global__ void stats_k(const float* __restrict__ gamma, const float* __restrict__ beta) {
    int o = threadIdx.x;
    if (o < CC) {
        const float inv = 1.f / (float)CNT_F;
        float mean = g_stats[o] * inv;
        float var  = g_stats[64 + o] * inv - mean*mean;
        float sc = gamma[o] * rsqrtf(var + 1e-5f);
        g_scale[o] = sc;
        g_shift[o] = beta[o] - mean*sc;
    }
}

__global__ void bn_apply(const float4* __restrict__ xv, float4* __restrict__ ov) {
    const float4* cv = reinterpret_cast<const float4*>(g_conv);
    const int n4 = TOTAL / 4;
    int stride = gridDim.x * blockDim.x;
    for (int i = blockIdx.x * blockDim.x + threadIdx.x; i < n4; i += stride) {
        int c = (i / 3200) & 63;
        float s  = __ldg(&g_scale[c]);
        float sh = __ldg(&g_shift[c]);
        float4 a = cv[i];
        float4 b = xv[i];
        float4 r;
        r.x = fmaxf(fmaf(s, a.x, sh) + b.x, 0.f);
        r.y = fmaxf(fmaf(s, a.y, sh) + b.y, 0.f);
        r.z = fmaxf(fmaf(s, a.z, sh) + b.z, 0.f);
        r.w = fmaxf(fmaf(s, a.w, sh) + b.w, 0.f);
        ov[i] = r;
    }
}

// ---------------------------------------------------------------------------
extern "C" void kernel_launch(void* const* d_in, const int* in_sizes, int n_in,
                              void* d_out, int out_size) {
    const float* x     = (const float*)d_in[0];
    const float* A     = (const float*)d_in[1];
    const float* W     = (const float*)d_in[2];
    // d_in[3] = b : cancels exactly under training-mode BatchNorm -> unused
    const float* gamma = (const float*)d_in[4];
    const float* beta  = (const float*)d_in[5];
    float* out = (float*)d_out;

    cudaFuncSetAttribute(conv_mma, cudaFuncAttributeMaxDynamicSharedMemorySize, SM_BYTES);

    prep_k<<<48, 256>>>(W);
    conv_mma<<<NN*(TT/TB), 128, SM_BYTES>>>(x, A);
    stats_k<<<1, 64>>>(gamma, beta);
    bn_apply<<<4096, 256>>>(reinterpret_cast<const float4*>(x),
                            reinterpret_cast<float4*>(out));
}

// round 7
// speedup vs baseline: 5.1420x; 2.6220x over previous
#include <cuda_runtime.h>
#include <cuda_fp16.h>
#include <cstdint>

#define NN 32
#define CC 64
#define TT 512
#define VV 25
#define HH 3
#define TB 8
#define TOTAL (NN*CC*TT*VV)     // 26214400
#define CNT_F (NN*TT*VV)        // 409600

// smem layout (bytes)
#define XS 264                  // X row stride in halves: 8*32 + 8 pad
#define XH_B 0                  // half [64][264]   = 33792 B
#define WH_B 33792              // half [192][72]   = 27648 B
#define AH_B 61440              // half [96][40]    = 7680 B
#define ST_B 69120              // float [128]      = 512 B
#define SM_BYTES 69632

__device__ float  g_conv[TOTAL];
__device__ __half g_Wh[HH*CC*CC];
__device__ float  g_stats[128];
__device__ float  g_scale[CC];
__device__ float  g_shift[CC];

__device__ __forceinline__ uint32_t smem_u32(const void* p) {
    uint32_t a;
    asm("{ .reg .u64 t; cvta.to.shared.u64 t, %1; cvt.u32.u64 %0, t; }" : "=r"(a) : "l"(p));
    return a;
}
__device__ __forceinline__ void ldmx4(uint32_t& r0, uint32_t& r1, uint32_t& r2, uint32_t& r3, uint32_t a) {
    asm volatile("ldmatrix.sync.aligned.m8n8.x4.shared.b16 {%0,%1,%2,%3},[%4];"
                 : "=r"(r0), "=r"(r1), "=r"(r2), "=r"(r3) : "r"(a));
}
__device__ __forceinline__ void ldmx2(uint32_t& r0, uint32_t& r1, uint32_t a) {
    asm volatile("ldmatrix.sync.aligned.m8n8.x2.shared.b16 {%0,%1},[%2];"
                 : "=r"(r0), "=r"(r1) : "r"(a));
}
__device__ __forceinline__ void ldmx2t(uint32_t& r0, uint32_t& r1, uint32_t a) {
    asm volatile("ldmatrix.sync.aligned.m8n8.x2.trans.shared.b16 {%0,%1},[%2];"
                 : "=r"(r0), "=r"(r1) : "r"(a));
}
__device__ __forceinline__ void mma16(float* c, const uint32_t* a, uint32_t b0, uint32_t b1) {
    asm volatile("mma.sync.aligned.m16n8k16.row.col.f32.f16.f16.f32 "
        "{%0,%1,%2,%3},{%4,%5,%6,%7},{%8,%9},{%0,%1,%2,%3};"
        : "+f"(c[0]), "+f"(c[1]), "+f"(c[2]), "+f"(c[3])
        : "r"(a[0]), "r"(a[1]), "r"(a[2]), "r"(a[3]), "r"(b0), "r"(b1));
}
__device__ __forceinline__ uint32_t h2u(__half2 h) { return *reinterpret_cast<uint32_t*>(&h); }

// ---------------------------------------------------------------------------
__global__ void prep_k(const float* __restrict__ W) {
    int i = blockIdx.x * blockDim.x + threadIdx.x;
    if (i < HH*CC*CC) g_Wh[i] = __float2half_rn(W[i]);
    if (i < 128) g_stats[i] = 0.f;
}

// ---------------------------------------------------------------------------
// conv: fp16 mma.m16n8k16, fp32 accum. CTA = (n, 8 t's). warp owns rows [16w,16w+16).
// stage1: Y[o, 32t+u] = W_h[o,c] @ X[c, 32t+u]  (X natural [c][s'], B via ldmatrix.trans)
// stage2: OUT[o, v]  += Y[o,u] @ A_h[v,u]^T     (A-frags in-register from Y)
// ---------------------------------------------------------------------------
__global__ __launch_bounds__(128, 3) void conv_mma(const float* __restrict__ x,
                                                   const float* __restrict__ A) {
    extern __shared__ char sm[];
    __half* Xh = (__half*)(sm + XH_B);
    __half* Wh = (__half*)(sm + WH_B);
    __half* Ah = (__half*)(sm + AH_B);
    float*  St = (float*)(sm + ST_B);

    const uint32_t smb = smem_u32(sm);
    const int tid  = threadIdx.x;
    const int warp = tid >> 5, lane = tid & 31;
    const int grp  = lane >> 2, tig = lane & 3;
    const int o0   = warp * 16;
    const int n    = blockIdx.x >> 6;            // 64 t-blocks per n
    const int t0   = (blockIdx.x & 63) * TB;

    St[tid] = 0.f;

    // --- W smem: [192][64] halves -> rows stride 72 ---
    {
        const uint32_t* sh = reinterpret_cast<const uint32_t*>(g_Wh);
        uint32_t* dh = reinterpret_cast<uint32_t*>(Wh);
        for (int i = tid; i < 192*32; i += 128) {
            int r = i >> 5, c2 = i & 31;
            dh[r*36 + c2] = sh[i];
        }
    }
    // --- A smem: [3*32][40] halves, zero-padded beyond 25x25 ---
    for (int i = tid; i < HH*32*32; i += 128) {
        int h = i >> 10, rem = i & 1023;
        int v = rem >> 5, u = rem & 31;
        float val = (v < VV && u < VV) ? A[(h*VV + v)*VV + u] : 0.f;
        Ah[(h*32 + v)*40 + u] = __float2half_rn(val);
    }
    // --- X pad: cols 32t+25..32t+31 zero, all 64 rows ---
    for (int i = tid; i < 64*56; i += 128) {
        int r = i / 56, k = i - r*56;
        int col = 32*(k/7) + 25 + (k%7);
        Xh[r*XS + col] = __float2half(0.f);
    }
    // --- X fill natural: Xh[c][32*(s/25) + s%25] from 200 contiguous floats/c ---
    {
        const float4* x4 = reinterpret_cast<const float4*>(x);
        for (int i = tid; i < CC*50; i += 128) {
            int c = i / 50, q = i - c*50;
            unsigned base = ((unsigned)(n*CC + c)*TT + t0)*VV;   // divisible by 4
            float4 v = x4[(base >> 2) + q];
            float vv[4] = {v.x, v.y, v.z, v.w};
            #pragma unroll
            for (int e = 0; e < 4; ++e) {
                int s = q*4 + e;
                int col = (s/25)*32 + (s - (s/25)*25);
                Xh[c*XS + col] = __float2half_rn(vv[e]);
            }
        }
    }
    __syncthreads();

    // --- hoist W fragments for ALL heads (a-frags, verified mapping) ---
    const int q4 = lane >> 3, r8 = lane & 7;
    const int wrow = r8 + ((q4 & 1) ? 8 : 0);
    const int wcol8 = (q4 & 2) ? 8 : 0;
    uint32_t whf[HH][4][4];
    #pragma unroll
    for (int h = 0; h < HH; ++h)
        #pragma unroll
        for (int kk = 0; kk < 4; ++kk) {
            uint32_t off = (uint32_t)(((h*64 + o0 + wrow)*72) + kk*16 + wcol8) * 2;
            ldmx4(whf[h][kk][0], whf[h][kk][1], whf[h][kk][2], whf[h][kk][3], smb + WH_B + off);
        }
    // --- hoist A (stage-2 B operand) fragments for ALL heads ---
    const int brow = lane & 7;
    const int bcol8 = (lane & 8) ? 8 : 0;
    uint32_t B2[HH][4][2][2];
    #pragma unroll
    for (int h = 0; h < HH; ++h)
        #pragma unroll
        for (int nv = 0; nv < 4; ++nv)
            #pragma unroll
            for (int kp = 0; kp < 2; ++kp) {
                uint32_t off = (uint32_t)(((h*32 + 8*nv + brow)*40) + kp*16 + bcol8) * 2;
                ldmx2(B2[h][nv][kp][0], B2[h][nv][kp][1], smb + AH_B + off);
            }

    // trans-ldmatrix row index for X (k within 16-tile)
    const int xrow = lane & 15;

    float st1a = 0.f, st2a = 0.f, st1b = 0.f, st2b = 0.f;   // stats for rows o0+grp, o0+grp+8
    const int r0 = o0 + grp, r1 = r0 + 8;

    for (int t = 0; t < TB; ++t) {
        float OUT[4][4];
        #pragma unroll
        for (int nv = 0; nv < 4; ++nv)
            #pragma unroll
            for (int e = 0; e < 4; ++e) OUT[nv][e] = 0.f;

        #pragma unroll
        for (int h = 0; h < HH; ++h) {
            // stage 1: Y tiles j=0..3 over u, k = c in 4 chunks of 16
            float Y[4][4];
            #pragma unroll
            for (int j = 0; j < 4; ++j)
                #pragma unroll
                for (int e = 0; e < 4; ++e) Y[j][e] = 0.f;

            #pragma unroll
            for (int kk = 0; kk < 4; ++kk) {
                #pragma unroll
                for (int j = 0; j < 4; ++j) {
                    uint32_t boff = (uint32_t)((16*kk + xrow)*XS + 32*t + 8*j) * 2;
                    uint32_t b0, b1;
                    ldmx2t(b0, b1, smb + XH_B + boff);
                    mma16(Y[j], whf[h][kk], b0, b1);
                }
            }
            // stage 2: in-register Y -> a-frags, accumulate OUT
            #pragma unroll
            for (int kp = 0; kp < 2; ++kp) {
                uint32_t ah[4];
                #pragma unroll
                for (int i = 0; i < 4; ++i) {
                    const float* yp = Y[2*kp + (i >> 1)];
                    float p  = yp[(i & 1) ? 2 : 0];
                    float qv = yp[(i & 1) ? 3 : 1];
                    ah[i] = h2u(__floats2half2_rn(p, qv));
                }
                #pragma unroll
                for (int nv = 0; nv < 4; ++nv)
                    mma16(OUT[nv], ah, B2[h][nv][kp][0], B2[h][nv][kp][1]);
            }
        }

        // per-t epilogue: direct scalar stores (warp-private rows), register stats
        unsigned base0 = ((unsigned)(n*CC + r0)*TT + t0 + t)*VV;
        unsigned base1 = ((unsigned)(n*CC + r1)*TT + t0 + t)*VV;
        #pragma unroll
        for (int nv = 0; nv < 4; ++nv) {
            int v0 = 8*nv + 2*tig;
            if (v0 < VV) {
                float a0 = OUT[nv][0], b0 = OUT[nv][2];
                g_conv[base0 + v0] = a0;
                g_conv[base1 + v0] = b0;
                st1a += a0; st2a += a0*a0;
                st1b += b0; st2b += b0*b0;
                if (v0 + 1 < VV) {
                    float a1 = OUT[nv][1], b1 = OUT[nv][3];
                    g_conv[base0 + v0 + 1] = a1;
                    g_conv[base1 + v0 + 1] = b1;
                    st1a += a1; st2a += a1*a1;
                    st1b += b1; st2b += b1*b1;
                }
            }
        }
    }

    // --- stats: smem reduce, one global atomic per tid ---
    atomicAdd(&St[r0],      st1a);
    atomicAdd(&St[64 + r0], st2a);
    atomicAdd(&St[r1],      st1b);
    atomicAdd(&St[64 + r1], st2b);
    __syncthreads();
    atomicAdd(&g_stats[tid], St[tid]);
}

// ---------------------------------------------------------------------------
__global__ void stats_k(const float* __restrict__ gamma, const float* __restrict__ beta) {
    int o = threadIdx.x;
    if (o < CC) {
        const float inv = 1.f / (float)CNT_F;
        float mean = g_stats[o] * inv;
        float var  = g_stats[64 + o] * inv - mean*mean;
        float sc = gamma[o] * rsqrtf(var + 1e-5f);
        g_scale[o] = sc;
        g_shift[o] = beta[o] - mean*sc;
    }
}

__global__ void bn_apply(const float4* __restrict__ xv, float4* __restrict__ ov) {
    const float4* cv = reinterpret_cast<const float4*>(g_conv);
    const int n4 = TOTAL / 4;
    int stride = gridDim.x * blockDim.x;
    for (int i = blockIdx.x * blockDim.x + threadIdx.x; i < n4; i += stride) {
        int c = (i / 3200) & 63;
        float s  = __ldg(&g_scale[c]);
        float sh = __ldg(&g_shift[c]);
        float4 a = cv[i];
        float4 b = xv[i];
        float4 r;
        r.x = fmaxf(fmaf(s, a.x, sh) + b.x, 0.f);
        r.y = fmaxf(fmaf(s, a.y, sh) + b.y, 0.f);
        r.z = fmaxf(fmaf(s, a.z, sh) + b.z, 0.f);
        r.w = fmaxf(fmaf(s, a.w, sh) + b.w, 0.f);
        ov[i] = r;
    }
}

// ---------------------------------------------------------------------------
extern "C" void kernel_launch(void* const* d_in, const int* in_sizes, int n_in,
                              void* d_out, int out_size) {
    const float* x     = (const float*)d_in[0];
    const float* A     = (const float*)d_in[1];
    const float* W     = (const float*)d_in[2];
    // d_in[3] = b : cancels exactly under training-mode BatchNorm -> unused
    const float* gamma = (const float*)d_in[4];
    const float* beta  = (const float*)d_in[5];
    float* out = (float*)d_out;

    cudaFuncSetAttribute(conv_mma, cudaFuncAttributeMaxDynamicSharedMemorySize, SM_BYTES);

    prep_k<<<48, 256>>>(W);
    conv_mma<<<NN*(TT/TB), 128, SM_BYTES>>>(x, A);
    stats_k<<<1, 64>>>(gamma, beta);
    bn_apply<<<4096, 256>>>(reinterpret_cast<const float4*>(x),
                            reinterpret_cast<float4*>(out));
}